// round 1
// baseline (speedup 1.0000x reference)
#include <cuda_runtime.h>

#define Bb 2
#define Nn 2048
#define Mm 64
#define Ff 128
#define H1 64
#define H2 64

// scratch (allocation-free rule: __device__ globals)
__device__ float g_buf[Bb * Nn * Ff];   // input-gradient per atom  [B*N, F]
__device__ float Ei_buf[Bb * Nn];       // per-atom energy

// ---------------------------------------------------------------------------
// Kernel 1: per-atom MLP forward + analytic input gradient.
// One block (128 threads) per atom. Weights are tiny -> L1/L2 resident.
// ---------------------------------------------------------------------------
__global__ __launch_bounds__(128) void mlp_kernel(
    const float* __restrict__ image,
    const float* __restrict__ W0,     // [H1, F]
    const float* __restrict__ W1,     // [H2, H1]
    const float* __restrict__ Wout)   // [1, H2]
{
    const int atom = blockIdx.x;        // b*N + n
    const int t    = threadIdx.x;       // 0..127

    __shared__ float xs[Ff];
    __shared__ float h0s[H1];
    __shared__ float t1s[H2];
    __shared__ float t0s[H1];
    __shared__ float eis[H2];

    xs[t] = image[atom * Ff + t];
    __syncthreads();

    // h0 = sigmoid(x @ W0^T)
    if (t < H1) {
        float acc = 0.f;
        const float* w = W0 + t * Ff;
#pragma unroll 8
        for (int f = 0; f < Ff; f++) acc = fmaf(xs[f], __ldg(w + f), acc);
        h0s[t] = 1.f / (1.f + __expf(-acc));
    }
    __syncthreads();

    // h1 = sigmoid(h0 @ W1^T);  t1 = h1*(1-h1)*Wout;  ei = h1*Wout
    if (t < H2) {
        float acc = 0.f;
        const float* w = W1 + t * H1;
#pragma unroll 8
        for (int k = 0; k < H1; k++) acc = fmaf(h0s[k], __ldg(w + k), acc);
        float h1 = 1.f / (1.f + __expf(-acc));
        float wo = __ldg(Wout + t);
        t1s[t] = h1 * (1.f - h1) * wo;
        eis[t] = h1 * wo;
    }
    __syncthreads();

    // g1 = t1 @ W1 ; t0 = h0*(1-h0)*g1       (threads 0..63)
    if (t < H1) {
        float acc = 0.f;
#pragma unroll 8
        for (int j = 0; j < H2; j++) acc = fmaf(t1s[j], __ldg(W1 + j * H1 + t), acc);
        float h0 = h0s[t];
        t0s[t] = h0 * (1.f - h0) * acc;
    }
    // Ei reduce in parallel (warp 2: threads 64..95)
    if (t >= 64 && t < 96) {
        int l = t - 64;
        float v = eis[l] + eis[l + 32];
#pragma unroll
        for (int off = 16; off > 0; off >>= 1)
            v += __shfl_down_sync(0xffffffffu, v, off);
        if (l == 0) Ei_buf[atom] = v;
    }
    __syncthreads();

    // g[f] = sum_k t0[k] * W0[k, f]  -- coalesced over f
    {
        float acc = 0.f;
#pragma unroll 8
        for (int k = 0; k < H1; k++) acc = fmaf(t0s[k], __ldg(W0 + k * Ff + t), acc);
        g_buf[atom * Ff + t] = acc;
    }
}

// ---------------------------------------------------------------------------
// Kernel 2: force = 1e10 * sum_m mask[m] * ( g[nei(m)] . dfeat[:, :, m, :, c] )
// One block (384 threads) per atom. Preload all 64 gathered g rows (masked)
// into 32 KB smem, then stream the 96 KB contiguous dfeat slice exactly once.
// Thread t -> c = t/128, f = t%128 (smem reads conflict-free, warp-uniform c).
// ---------------------------------------------------------------------------
__global__ __launch_bounds__(384) void force_kernel(
    const int*   __restrict__ neighbor,   // [B*N, M]
    const float* __restrict__ dfeat,      // [B*N, M, F, 3]
    float*       __restrict__ out_force)  // [B*N, 3]
{
    const int atom = blockIdx.x;
    const int b    = atom >> 11;            // N = 2048
    const int t    = threadIdx.x;

    __shared__ float sg[Mm * Ff];            // 32 KB: gathered+masked g rows
    __shared__ float wsum[12];

    for (int i = t; i < Mm * Ff; i += 384) {
        int m = i >> 7;
        int f = i & 127;
        int nei = __ldg(neighbor + atom * Mm + m);
        sg[i] = (nei > 0) ? g_buf[((size_t)(b * Nn + nei - 1)) * Ff + f] : 0.f;
    }
    __syncthreads();

    const int c = t >> 7;       // 0..2
    const int f = t & 127;
    const float* dp = dfeat + (size_t)atom * (Mm * Ff * 3) + f * 3 + c;

    float a0 = 0.f, a1 = 0.f, a2 = 0.f, a3 = 0.f;
#pragma unroll 4
    for (int m = 0; m < Mm; m += 4) {
        a0 = fmaf(sg[(m + 0) * Ff + f], __ldg(dp + (size_t)(m + 0) * (Ff * 3)), a0);
        a1 = fmaf(sg[(m + 1) * Ff + f], __ldg(dp + (size_t)(m + 1) * (Ff * 3)), a1);
        a2 = fmaf(sg[(m + 2) * Ff + f], __ldg(dp + (size_t)(m + 2) * (Ff * 3)), a2);
        a3 = fmaf(sg[(m + 3) * Ff + f], __ldg(dp + (size_t)(m + 3) * (Ff * 3)), a3);
    }
    float acc = (a0 + a1) + (a2 + a3);

#pragma unroll
    for (int off = 16; off > 0; off >>= 1)
        acc += __shfl_down_sync(0xffffffffu, acc, off);

    const int w = t >> 5;                    // warp id 0..11
    if ((t & 31) == 0) wsum[w] = acc;
    __syncthreads();

    if (t < 3) {
        float s = (wsum[t * 4] + wsum[t * 4 + 1]) + (wsum[t * 4 + 2] + wsum[t * 4 + 3]);
        out_force[atom * 3 + t] = s * 1e10f;
    }
}

// ---------------------------------------------------------------------------
// Kernel 3: deterministic Etot = sum_n Ei  (double accumulation)
// ---------------------------------------------------------------------------
__global__ __launch_bounds__(256) void etot_kernel(float* __restrict__ out)
{
    const int b = blockIdx.x;
    const int t = threadIdx.x;
    __shared__ double sd[256];

    double s = 0.0;
    for (int n = t; n < Nn; n += 256) s += (double)Ei_buf[b * Nn + n];
    sd[t] = s;
    __syncthreads();
#pragma unroll
    for (int k = 128; k > 0; k >>= 1) {
        if (t < k) sd[t] += sd[t + k];
        __syncthreads();
    }
    if (t == 0) out[b] = (float)sd[0];
}

// ---------------------------------------------------------------------------
// Launch. Inputs (metadata order): image, dfeat, neighbor, Egroup_weight,
// divider, W0, W1, Wout.  Egroup_weight/divider are unused by the reference.
// Output: [Etot (B=2 floats), force (B*N*3 = 12288 floats)] flattened.
// ---------------------------------------------------------------------------
extern "C" void kernel_launch(void* const* d_in, const int* in_sizes, int n_in,
                              void* d_out, int out_size)
{
    const float* image    = (const float*)d_in[0];
    const float* dfeat    = (const float*)d_in[1];
    const int*   neighbor = (const int*)  d_in[2];
    const float* W0       = (const float*)d_in[5];
    const float* W1       = (const float*)d_in[6];
    const float* Wout     = (const float*)d_in[7];
    float* out = (float*)d_out;

    mlp_kernel<<<Bb * Nn, 128>>>(image, W0, W1, Wout);
    etot_kernel<<<Bb, 256>>>(out);
    force_kernel<<<Bb * Nn, 384>>>(neighbor, dfeat, out + 2);
}

// round 2
// speedup vs baseline: 2.3358x; 2.3358x over previous
#include <cuda_runtime.h>

#define Bb 2
#define Nn 2048
#define Mm 64
#define Ff 128
#define H1 64
#define H2 64
#define TILE 8          // atoms per MLP block
#define MLP_THREADS 512 // TILE * 64

// scratch (allocation-free rule: __device__ globals)
__device__ float g_buf[Bb * Nn * Ff];   // input-gradient per atom  [B*N, F]
__device__ float Ei_buf[Bb * Nn];       // per-atom energy

// ---------------------------------------------------------------------------
// Kernel 1: batched per-atom MLP forward + analytic input gradient.
// One 512-thread block per 8 atoms. Weights staged ONCE per block into smem
// in padded-transposed layout (stride 65): conflict-free in BOTH directions
// (forward: consecutive n at fixed f; backward: consecutive f at fixed k,
//  since 65 mod 32 == 1).
// Thread mapping: a = t>>6 (atom in tile), n = t&63 (neuron).
// ---------------------------------------------------------------------------
__global__ __launch_bounds__(MLP_THREADS) void mlp_kernel(
    const float* __restrict__ image,
    const float* __restrict__ W0,     // [H1, F]   row-major
    const float* __restrict__ W1,     // [H2, H1]  row-major
    const float* __restrict__ Wout)   // [1, H2]
{
    extern __shared__ float sm[];
    float* W0T   = sm;                      // [F][65]  = W0T[f*65+n] = W0[n][f]
    float* W1T   = W0T + Ff * 65;           // [H1][65] = W1T[k*65+j] = W1[j][k]
    float* WoS   = W1T + H1 * 65;           // [64]
    float* xs    = WoS + 64;                // [TILE][128]
    float* h0s   = xs  + TILE * Ff;         // [TILE][64]
    float* t1s   = h0s + TILE * H1;         // [TILE][64]
    float* t0s   = t1s + TILE * H2;         // [TILE][64]
    float* ePart = t0s + TILE * H1;         // [TILE][2]

    const int t    = threadIdx.x;
    const int base = blockIdx.x * TILE;     // first atom of the tile
    const int a    = t >> 6;                // 0..7
    const int n    = t & 63;                // 0..63

    // ---- stage weights (coalesced global reads, conflict-free smem stores) ----
    for (int i = t; i < H1 * Ff; i += MLP_THREADS) {
        int r = i >> 7, f = i & 127;        // W0[r][f]
        W0T[f * 65 + r] = W0[i];
    }
    for (int i = t; i < H2 * H1; i += MLP_THREADS) {
        int j = i >> 6, k = i & 63;         // W1[j][k]
        W1T[k * 65 + j] = W1[i];
    }
    if (t < H2) WoS[t] = Wout[t];
    // ---- stage inputs ----
    for (int i = t; i < TILE * Ff; i += MLP_THREADS)
        xs[i] = image[(size_t)base * Ff + i];
    __syncthreads();

    const float* xrow = xs + a * Ff;

    // ---- phase 1: h0 = sigmoid(x @ W0^T) ----
    {
        float acc = 0.f;
#pragma unroll
        for (int f = 0; f < Ff; f++)
            acc = fmaf(xrow[f], W0T[f * 65 + n], acc);
        h0s[a * 64 + n] = 1.f / (1.f + __expf(-acc));
    }
    __syncthreads();

    // ---- phase 2: h1, t1 = h1(1-h1)*Wout, Ei partials ----
    {
        float acc = 0.f;
#pragma unroll
        for (int k = 0; k < H1; k++)
            acc = fmaf(h0s[a * 64 + k], W1T[k * 65 + n], acc);
        float h1 = 1.f / (1.f + __expf(-acc));
        float wo = WoS[n];
        t1s[a * 64 + n] = h1 * (1.f - h1) * wo;
        float ei = h1 * wo;
#pragma unroll
        for (int off = 16; off > 0; off >>= 1)
            ei += __shfl_down_sync(0xffffffffu, ei, off);
        if ((n & 31) == 0) ePart[a * 2 + (n >> 5)] = ei;
    }
    __syncthreads();

    // ---- phase 3: g1 = t1 @ W1 ; t0 = h0(1-h0)*g1 ----
    {
        float acc = 0.f;
#pragma unroll
        for (int j = 0; j < H2; j++)
            acc = fmaf(t1s[a * 64 + j], W1T[n * 65 + j], acc);  // W1[j][n]
        float h0 = h0s[a * 64 + n];
        t0s[a * 64 + n] = h0 * (1.f - h0) * acc;
        if (n == 0) Ei_buf[base + a] = ePart[a * 2] + ePart[a * 2 + 1];
    }
    __syncthreads();

    // ---- phase 4: g[f] = sum_k t0[k] * W0[k][f]  (2 f's per thread) ----
    {
        const int f0 = n, f1 = n + 64;
        float acc0 = 0.f, acc1 = 0.f;
#pragma unroll
        for (int k = 0; k < H1; k++) {
            float tv = t0s[a * 64 + k];
            acc0 = fmaf(tv, W0T[f0 * 65 + k], acc0);
            acc1 = fmaf(tv, W0T[f1 * 65 + k], acc1);
        }
        float* go = g_buf + (size_t)(base + a) * Ff;
        go[f0] = acc0;
        go[f1] = acc1;
    }
}

// ---------------------------------------------------------------------------
// Kernel 2: force = 1e10 * sum_m mask[m] * ( g[nei(m)] . dfeat[atom, m, :, c] )
// One block (384 threads) per atom. Preload all 64 gathered g rows (masked)
// into 32 KB smem, then stream the 96 KB contiguous dfeat slice exactly once.
// ---------------------------------------------------------------------------
__global__ __launch_bounds__(384) void force_kernel(
    const int*   __restrict__ neighbor,   // [B*N, M]
    const float* __restrict__ dfeat,      // [B*N, M, F, 3]
    float*       __restrict__ out_force)  // [B*N, 3]
{
    const int atom = blockIdx.x;
    const int b    = atom >> 11;            // N = 2048
    const int t    = threadIdx.x;

    __shared__ float sg[Mm * Ff];            // 32 KB: gathered+masked g rows
    __shared__ float wsum[12];

    for (int i = t; i < Mm * Ff; i += 384) {
        int m = i >> 7;
        int f = i & 127;
        int nei = __ldg(neighbor + atom * Mm + m);
        sg[i] = (nei > 0) ? g_buf[((size_t)(b * Nn + nei - 1)) * Ff + f] : 0.f;
    }
    __syncthreads();

    const int c = t >> 7;       // 0..2
    const int f = t & 127;
    const float* dp = dfeat + (size_t)atom * (Mm * Ff * 3) + f * 3 + c;

    float a0 = 0.f, a1 = 0.f, a2 = 0.f, a3 = 0.f;
#pragma unroll 4
    for (int m = 0; m < Mm; m += 4) {
        a0 = fmaf(sg[(m + 0) * Ff + f], __ldg(dp + (size_t)(m + 0) * (Ff * 3)), a0);
        a1 = fmaf(sg[(m + 1) * Ff + f], __ldg(dp + (size_t)(m + 1) * (Ff * 3)), a1);
        a2 = fmaf(sg[(m + 2) * Ff + f], __ldg(dp + (size_t)(m + 2) * (Ff * 3)), a2);
        a3 = fmaf(sg[(m + 3) * Ff + f], __ldg(dp + (size_t)(m + 3) * (Ff * 3)), a3);
    }
    float acc = (a0 + a1) + (a2 + a3);

#pragma unroll
    for (int off = 16; off > 0; off >>= 1)
        acc += __shfl_down_sync(0xffffffffu, acc, off);

    const int w = t >> 5;                    // warp id 0..11
    if ((t & 31) == 0) wsum[w] = acc;
    __syncthreads();

    if (t < 3) {
        float s = (wsum[t * 4] + wsum[t * 4 + 1]) + (wsum[t * 4 + 2] + wsum[t * 4 + 3]);
        out_force[atom * 3 + t] = s * 1e10f;
    }
}

// ---------------------------------------------------------------------------
// Kernel 3: deterministic Etot = sum_n Ei  (double accumulation)
// ---------------------------------------------------------------------------
__global__ __launch_bounds__(256) void etot_kernel(float* __restrict__ out)
{
    const int b = blockIdx.x;
    const int t = threadIdx.x;
    __shared__ double sd[256];

    double s = 0.0;
    for (int n = t; n < Nn; n += 256) s += (double)Ei_buf[b * Nn + n];
    sd[t] = s;
    __syncthreads();
#pragma unroll
    for (int k = 128; k > 0; k >>= 1) {
        if (t < k) sd[t] += sd[t + k];
        __syncthreads();
    }
    if (t == 0) out[b] = (float)sd[0];
}

// ---------------------------------------------------------------------------
// Launch. Inputs (metadata order): image, dfeat, neighbor, Egroup_weight,
// divider, W0, W1, Wout.  Egroup_weight/divider are unused by the reference.
// Output: [Etot (B=2 floats), force (B*N*3 = 12288 floats)] flattened.
// ---------------------------------------------------------------------------
extern "C" void kernel_launch(void* const* d_in, const int* in_sizes, int n_in,
                              void* d_out, int out_size)
{
    const float* image    = (const float*)d_in[0];
    const float* dfeat    = (const float*)d_in[1];
    const int*   neighbor = (const int*)  d_in[2];
    const float* W0       = (const float*)d_in[5];
    const float* W1       = (const float*)d_in[6];
    const float* Wout     = (const float*)d_in[7];
    float* out = (float*)d_out;

    const int smem_bytes =
        (Ff * 65 + H1 * 65 + 64 + TILE * Ff + 3 * TILE * 64 + 2 * TILE) * (int)sizeof(float);
    cudaFuncSetAttribute(mlp_kernel, cudaFuncAttributeMaxDynamicSharedMemorySize, smem_bytes);

    mlp_kernel<<<(Bb * Nn) / TILE, MLP_THREADS, smem_bytes>>>(image, W0, W1, Wout);
    etot_kernel<<<Bb, 256>>>(out);
    force_kernel<<<Bb * Nn, 384>>>(neighbor, dfeat, out + 2);
}

// round 3
// speedup vs baseline: 2.7905x; 1.1947x over previous
#include <cuda_runtime.h>

#define Bb 2
#define Nn 2048
#define Mm 64
#define Ff 128
#define H1 64
#define H2 64
#define TILE 16         // atoms per MLP block
#define MLP_THREADS 512 // 8 pairs x 64 neurons

// scratch (allocation-free rule: __device__ globals)
__device__ float g_buf[Bb * Nn * Ff];   // input-gradient per atom  [B*N, F]
__device__ float Ei_buf[Bb * Nn];       // per-atom energy

__device__ __forceinline__ float sigmoidf(float z) {
    return 1.f / (1.f + __expf(-z));
}

// ---------------------------------------------------------------------------
// Kernel 1: batched per-atom MLP forward + analytic input gradient.
// 512 threads / 16 atoms. thread -> (pair p = t>>6, neuron n = t&63); each
// thread computes 2 atoms so every weight LDS is reused twice (~1.3 LDS/FMA).
// Weights in smem, padded-transposed stride 65 (conflict-free both directions).
// ---------------------------------------------------------------------------
__global__ __launch_bounds__(MLP_THREADS) void mlp_kernel(
    const float* __restrict__ image,
    const float* __restrict__ W0,     // [H1, F]   row-major
    const float* __restrict__ W1,     // [H2, H1]  row-major
    const float* __restrict__ Wout)   // [1, H2]
{
    extern __shared__ float sm[];
    float* W0T   = sm;                      // [F][65]:  W0T[f*65+n] = W0[n][f]
    float* W1T   = W0T + Ff * 65;           // [H1][65]: W1T[k*65+j] = W1[j][k]
    float* WoS   = W1T + H1 * 65;           // [64]
    float* xs    = WoS + 64;                // [TILE][128]
    float* h0s   = xs  + TILE * Ff;         // [TILE][64]
    float* t1s   = h0s + TILE * H1;         // [TILE][64]
    float* t0s   = t1s + TILE * H2;         // [TILE][64]
    float* ePart = t0s + TILE * H1;         // [TILE][2]

    const int t    = threadIdx.x;
    const int base = blockIdx.x * TILE;
    const int p    = t >> 6;                // pair 0..7
    const int n    = t & 63;                // neuron 0..63
    const int a0   = 2 * p, a1 = 2 * p + 1; // atoms within tile

    // ---- stage weights + inputs (coalesced) ----
    for (int i = t; i < H1 * Ff; i += MLP_THREADS) {
        int r = i >> 7, f = i & 127;
        W0T[f * 65 + r] = W0[i];
    }
    for (int i = t; i < H2 * H1; i += MLP_THREADS) {
        int j = i >> 6, k = i & 63;
        W1T[k * 65 + j] = W1[i];
    }
    if (t < H2) WoS[t] = Wout[t];
    for (int i = t; i < TILE * Ff; i += MLP_THREADS)
        xs[i] = image[(size_t)base * Ff + i];
    __syncthreads();

    const float* x0 = xs + a0 * Ff;
    const float* x1 = xs + a1 * Ff;

    // ---- phase 1: h0 = sigmoid(x @ W0^T) ----
    {
        float s0a = 0.f, s0b = 0.f, s1a = 0.f, s1b = 0.f;
#pragma unroll
        for (int f = 0; f < Ff; f += 2) {
            float wa = W0T[f * 65 + n];
            float wb = W0T[(f + 1) * 65 + n];
            s0a = fmaf(x0[f],     wa, s0a);
            s0b = fmaf(x0[f + 1], wb, s0b);
            s1a = fmaf(x1[f],     wa, s1a);
            s1b = fmaf(x1[f + 1], wb, s1b);
        }
        h0s[a0 * 64 + n] = sigmoidf(s0a + s0b);
        h0s[a1 * 64 + n] = sigmoidf(s1a + s1b);
    }
    __syncthreads();

    // ---- phase 2: h1, t1 = h1(1-h1)*Wout, Ei partials ----
    {
        float s0a = 0.f, s0b = 0.f, s1a = 0.f, s1b = 0.f;
#pragma unroll
        for (int k = 0; k < H1; k += 2) {
            float wa = W1T[k * 65 + n];
            float wb = W1T[(k + 1) * 65 + n];
            s0a = fmaf(h0s[a0 * 64 + k],     wa, s0a);
            s0b = fmaf(h0s[a0 * 64 + k + 1], wb, s0b);
            s1a = fmaf(h0s[a1 * 64 + k],     wa, s1a);
            s1b = fmaf(h0s[a1 * 64 + k + 1], wb, s1b);
        }
        float wo = WoS[n];
        float h1_0 = sigmoidf(s0a + s0b);
        float h1_1 = sigmoidf(s1a + s1b);
        t1s[a0 * 64 + n] = h1_0 * (1.f - h1_0) * wo;
        t1s[a1 * 64 + n] = h1_1 * (1.f - h1_1) * wo;
        float e0 = h1_0 * wo, e1 = h1_1 * wo;
#pragma unroll
        for (int off = 16; off > 0; off >>= 1) {
            e0 += __shfl_down_sync(0xffffffffu, e0, off);
            e1 += __shfl_down_sync(0xffffffffu, e1, off);
        }
        if ((n & 31) == 0) {
            int half = n >> 5;
            ePart[a0 * 2 + half] = e0;
            ePart[a1 * 2 + half] = e1;
        }
    }
    __syncthreads();

    // ---- phase 3: g1 = t1 @ W1 ; t0 = h0(1-h0)*g1 ----
    {
        float s0a = 0.f, s0b = 0.f, s1a = 0.f, s1b = 0.f;
#pragma unroll
        for (int j = 0; j < H2; j += 2) {
            float wa = W1T[n * 65 + j];          // = W1[j][n]
            float wb = W1T[n * 65 + j + 1];
            s0a = fmaf(t1s[a0 * 64 + j],     wa, s0a);
            s0b = fmaf(t1s[a0 * 64 + j + 1], wb, s0b);
            s1a = fmaf(t1s[a1 * 64 + j],     wa, s1a);
            s1b = fmaf(t1s[a1 * 64 + j + 1], wb, s1b);
        }
        float h00 = h0s[a0 * 64 + n];
        float h01 = h0s[a1 * 64 + n];
        t0s[a0 * 64 + n] = h00 * (1.f - h00) * (s0a + s0b);
        t0s[a1 * 64 + n] = h01 * (1.f - h01) * (s1a + s1b);
        if (n == 0) {
            Ei_buf[base + a0] = ePart[a0 * 2] + ePart[a0 * 2 + 1];
            Ei_buf[base + a1] = ePart[a1 * 2] + ePart[a1 * 2 + 1];
        }
    }
    __syncthreads();

    // ---- phase 4: g[f] = sum_k t0[k] * W0[k][f]  (f = n and n+64, 2 atoms) ----
    {
        const int f0 = n, f1 = n + 64;
        float g00 = 0.f, g01 = 0.f, g10 = 0.f, g11 = 0.f;
#pragma unroll
        for (int k = 0; k < H1; k++) {
            float w0 = W0T[f0 * 65 + k];
            float w1 = W0T[f1 * 65 + k];
            float ta = t0s[a0 * 64 + k];
            float tb = t0s[a1 * 64 + k];
            g00 = fmaf(ta, w0, g00);
            g01 = fmaf(ta, w1, g01);
            g10 = fmaf(tb, w0, g10);
            g11 = fmaf(tb, w1, g11);
        }
        float* go0 = g_buf + (size_t)(base + a0) * Ff;
        float* go1 = g_buf + (size_t)(base + a1) * Ff;
        go0[f0] = g00; go0[f1] = g01;
        go1[f0] = g10; go1[f1] = g11;
    }
}

// ---------------------------------------------------------------------------
// Kernel 2: force = 1e10 * sum_m mask[m] * ( g[nei(m)] . dfeat[atom, m, :, c] )
// One block (384 threads) per atom. Stage 64 gathered g rows in smem (float4),
// then stream the 96 KB dfeat slice with contiguous LDG.128 (each sector read
// exactly once). Thread-invariant mapping: q = t + 384*it, r4 = t%96,
// case = r4%3, f0 = 4*r4/3; only m = t/96 + 4*it advances.
// ---------------------------------------------------------------------------
__global__ __launch_bounds__(384) void force_kernel(
    const int*   __restrict__ neighbor,   // [B*N, M]
    const float* __restrict__ dfeat,      // [B*N, M, F, 3]
    float*       __restrict__ out_force)  // [B*N, 3]
{
    const int atom = blockIdx.x;
    const int b    = atom >> 11;            // N = 2048
    const int t    = threadIdx.x;

    __shared__ float sg[Mm * Ff];            // 32 KB gathered+masked g rows
    __shared__ float wsum[12][3];

    // stage gathered g rows as float4 (coalesced; L2-resident source)
    {
        float4*       sg4 = (float4*)sg;
        const float4* g4  = (const float4*)g_buf;
        for (int i = t; i < Mm * (Ff / 4); i += 384) {
            int m  = i >> 5;                 // Ff/4 = 32 float4 per row
            int f4 = i & 31;
            int nei = __ldg(neighbor + atom * Mm + m);
            sg4[i] = (nei > 0)
                   ? g4[((size_t)(b * Nn + nei - 1)) * (Ff / 4) + f4]
                   : make_float4(0.f, 0.f, 0.f, 0.f);
        }
    }
    __syncthreads();

    const int r4  = t % 96;                  // loop-invariant per thread
    const int m0  = t / 96;                  // 0..3
    const int cse = r4 % 3;
    const int f0  = (4 * r4) / 3;            // 0..126

    const float4* dp = (const float4*)(dfeat + (size_t)atom * (Mm * Ff * 3)) + t;

    // a_k accumulates component c = (cse + k) % 3
    float A0 = 0.f, A1 = 0.f, A2 = 0.f;
#pragma unroll
    for (int it = 0; it < 16; it++) {
        const int m = m0 + 4 * it;
        float4 v = __ldg(dp + (size_t)it * 384);
        float s0 = sg[m * Ff + f0];
        float s1 = sg[m * Ff + f0 + 1];
        float sy = (cse == 2) ? s1 : s0;     // elem 1 crosses f iff cse==2
        float sz = (cse == 0) ? s0 : s1;     // elem 2 stays at f iff cse==0
        A0 = fmaf(v.x, s0, A0);
        A1 = fmaf(v.y, sy, A1);
        A2 = fmaf(v.z, sz, A2);
        A0 = fmaf(v.w, s1, A0);
    }
    // rotate (A0,A1,A2) -> (c0,c1,c2):  A_k holds c = (cse+k)%3
    float c0 = (cse == 0) ? A0 : (cse == 1) ? A2 : A1;
    float c1 = (cse == 0) ? A1 : (cse == 1) ? A0 : A2;
    float c2 = (cse == 0) ? A2 : (cse == 1) ? A1 : A0;

#pragma unroll
    for (int off = 16; off > 0; off >>= 1) {
        c0 += __shfl_down_sync(0xffffffffu, c0, off);
        c1 += __shfl_down_sync(0xffffffffu, c1, off);
        c2 += __shfl_down_sync(0xffffffffu, c2, off);
    }
    const int w = t >> 5;
    if ((t & 31) == 0) { wsum[w][0] = c0; wsum[w][1] = c1; wsum[w][2] = c2; }
    __syncthreads();

    if (t < 3) {
        float s = 0.f;
#pragma unroll
        for (int w2 = 0; w2 < 12; w2++) s += wsum[w2][t];
        out_force[atom * 3 + t] = s * 1e10f;
    }
}

// ---------------------------------------------------------------------------
// Kernel 3: deterministic Etot = sum_n Ei  (double accumulation)
// ---------------------------------------------------------------------------
__global__ __launch_bounds__(256) void etot_kernel(float* __restrict__ out)
{
    const int b = blockIdx.x;
    const int t = threadIdx.x;
    __shared__ double sd[256];

    double s = 0.0;
    for (int n = t; n < Nn; n += 256) s += (double)Ei_buf[b * Nn + n];
    sd[t] = s;
    __syncthreads();
#pragma unroll
    for (int k = 128; k > 0; k >>= 1) {
        if (t < k) sd[t] += sd[t + k];
        __syncthreads();
    }
    if (t == 0) out[b] = (float)sd[0];
}

// ---------------------------------------------------------------------------
// Launch. Inputs (metadata order): image, dfeat, neighbor, Egroup_weight,
// divider, W0, W1, Wout.  Egroup_weight/divider are unused by the reference.
// Output: [Etot (B=2 floats), force (B*N*3 = 12288 floats)] flattened.
// ---------------------------------------------------------------------------
extern "C" void kernel_launch(void* const* d_in, const int* in_sizes, int n_in,
                              void* d_out, int out_size)
{
    const float* image    = (const float*)d_in[0];
    const float* dfeat    = (const float*)d_in[1];
    const int*   neighbor = (const int*)  d_in[2];
    const float* W0       = (const float*)d_in[5];
    const float* W1       = (const float*)d_in[6];
    const float* Wout     = (const float*)d_in[7];
    float* out = (float*)d_out;

    const int smem_bytes =
        (Ff * 65 + H1 * 65 + 64 + TILE * Ff + 3 * TILE * 64 + 2 * TILE) * (int)sizeof(float);
    static bool attr_set = false;
    cudaFuncSetAttribute(mlp_kernel, cudaFuncAttributeMaxDynamicSharedMemorySize, smem_bytes);
    (void)attr_set;

    mlp_kernel<<<(Bb * Nn) / TILE, MLP_THREADS, smem_bytes>>>(image, W0, W1, Wout);
    etot_kernel<<<Bb, 256>>>(out);
    force_kernel<<<Bb * Nn, 384>>>(neighbor, dfeat, out + 2);
}